// round 1
// baseline (speedup 1.0000x reference)
#include <cuda_runtime.h>

#define T 256
#define H 1024
#define E 64
#define IDIM 512
#define SI 2048
#define TOPK 6

typedef unsigned long long ull;

// ---------------- device scratch (no allocations allowed) ----------------
__device__ int   g_cnt[E];
__device__ int   g_slot[E * T];   // assignment slot (t*6+k) per expert-list entry
__device__ int   g_tok[E * T];    // token index per expert-list entry
__device__ float g_wt[E * T];     // combine weight per expert-list entry
__device__ float g_act[T * TOPK * IDIM];  // 3 MB: silu(h1)*h3 per assignment
__device__ float g_eo[T * TOPK * H];      // 6 MB: weighted expert outputs
__device__ float g_sact[T * SI];          // 2 MB: shared-expert activation

// ---------------- f32x2 packed helpers ----------------
__device__ __forceinline__ void fma2(ull &d, ull a, ull b) {
    asm("fma.rn.f32x2 %0, %1, %2, %0;" : "+l"(d) : "l"(a), "l"(b));
}
__device__ __forceinline__ ull dup2(float x) {
    ull r;
    asm("mov.b64 %0, {%1, %2};" : "=l"(r) : "f"(x), "f"(x));
    return r;
}
__device__ __forceinline__ float lo2(ull v) { return __uint_as_float((unsigned)(v & 0xffffffffull)); }
__device__ __forceinline__ float hi2(ull v) { return __uint_as_float((unsigned)(v >> 32)); }

__device__ __forceinline__ float silu(float v) { return v / (1.0f + expf(-v)); }

// ---------------- init ----------------
__global__ void init_kernel() {
    if (threadIdx.x < E) g_cnt[threadIdx.x] = 0;
}

// ---------------- gate + routing: one block per token ----------------
__global__ void gate_routing_kernel(const float* __restrict__ x,
                                    const float* __restrict__ gw,
                                    const float* __restrict__ ebias) {
    __shared__ float xs[H];
    __shared__ float part[256];
    __shared__ float logits[E];
    int t = blockIdx.x, tid = threadIdx.x;

    ((float4*)xs)[tid] = ((const float4*)(x + (size_t)t * H))[tid];
    __syncthreads();

    int e = tid >> 2, q = tid & 3;
    const float* gr = gw + (size_t)e * H + q * 256;
    const float* xr = xs + q * 256;
    float s = 0.0f;
#pragma unroll 8
    for (int k = 0; k < 256; k += 4) {
        float4 g = *(const float4*)(gr + k);
        float4 xv = *(const float4*)(xr + k);
        s += g.x * xv.x + g.y * xv.y + g.z * xv.z + g.w * xv.w;
    }
    part[tid] = s;
    __syncthreads();
    if (tid < E) logits[tid] = part[tid * 4] + part[tid * 4 + 1] + part[tid * 4 + 2] + part[tid * 4 + 3];
    __syncthreads();

    if (tid == 0) {
        float sc[E], swb[E];
        for (int i = 0; i < E; i++) {
            float l = logits[i];
            sc[i] = 1.0f / (1.0f + expf(-l));
            swb[i] = sc[i] + ebias[i];
        }
        // group scores: sum of top-2 per group of 8
        float gs[8];
        for (int g = 0; g < 8; g++) {
            float m1 = -1e30f, m2 = -1e30f;
            for (int j = 0; j < 8; j++) {
                float v = swb[g * 8 + j];
                if (v > m1) { m2 = m1; m1 = v; }
                else if (v > m2) { m2 = v; }
            }
            gs[g] = m1 + m2;
        }
        // top-4 groups (strict >: lowest index wins ties, matches lax.top_k)
        bool gsel[8];
        for (int g = 0; g < 8; g++) gsel[g] = false;
        for (int r = 0; r < 4; r++) {
            int best = 0; float bv = -1e30f;
            for (int g = 0; g < 8; g++)
                if (!gsel[g] && gs[g] > bv) { bv = gs[g]; best = g; }
            gsel[best] = true;
        }
        // top-6 experts of swb * groupmask (masked-out = 0)
        bool picked[E];
        for (int i = 0; i < E; i++) picked[i] = false;
        int idx[TOPK];
        float wsum = 0.0f;
        for (int r = 0; r < TOPK; r++) {
            int best = 0; float bv = -1e30f;
            for (int i = 0; i < E; i++) {
                if (picked[i]) continue;
                float v = gsel[i >> 3] ? swb[i] : 0.0f;
                if (v > bv) { bv = v; best = i; }
            }
            picked[best] = true;
            idx[r] = best;
            wsum += sc[best];
        }
        float inv = 2.5f / (wsum + 1e-20f);
        for (int r = 0; r < TOPK; r++) {
            int ee = idx[r];
            int pos = atomicAdd(&g_cnt[ee], 1);
            g_slot[ee * T + pos] = t * TOPK + r;
            g_tok[ee * T + pos] = t;
            g_wt[ee * T + pos] = sc[ee] * inv;
        }
    }
}

// ================= tiled GEMM kernels =================
// Common tile: M=32, N=128, KC=32, 128 threads, micro-tile 4m x 8i (i-pairs for f32x2).
// smem transposed [k][row]; strides 36 (A) / 132 (B) keep float4/u64 alignment
// and conflict-free compute reads.

#define SA 36
#define SB 132

// ---- stage A: act = silu(X_e @ w1_e^T) * (X_e @ w3_e^T), gathered rows ----
__global__ __launch_bounds__(128) void stageA_kernel(const float* __restrict__ x,
                                                     const float* __restrict__ w1,
                                                     const float* __restrict__ w3) {
    int e = blockIdx.y;
    int n = g_cnt[e];
    int m0 = blockIdx.z * 32;
    if (m0 >= n) return;
    int i0 = blockIdx.x * 128;
    int tid = threadIdx.x;

    __shared__ float As[32 * SA];
    __shared__ float B1s[32 * SB];
    __shared__ float B3s[32 * SB];
    __shared__ int toks[32];
    __shared__ int slots[32];

    int mcnt = min(32, n - m0);
    if (tid < 32) {
        bool v = tid < mcnt;
        toks[tid] = v ? g_tok[e * T + m0 + tid] : 0;
        slots[tid] = v ? g_slot[e * T + m0 + tid] : 0;
    }
    __syncthreads();

    ull acc1[4][4], acc3[4][4];
#pragma unroll
    for (int a = 0; a < 4; a++)
#pragma unroll
        for (int b = 0; b < 4; b++) { acc1[a][b] = 0ull; acc3[a][b] = 0ull; }

    int tx = tid & 15, ty = tid >> 4;
    const float* w1base = w1 + ((size_t)e * IDIM + i0) * H;
    const float* w3base = w3 + ((size_t)e * IDIM + i0) * H;

    for (int kt = 0; kt < H; kt += 32) {
#pragma unroll
        for (int l = 0; l < 2; l++) {
            int idx = tid + l * 128;
            int m = idx >> 3, kq = idx & 7;
            float4 v = make_float4(0.f, 0.f, 0.f, 0.f);
            if (m < mcnt) v = *(const float4*)&x[(size_t)toks[m] * H + kt + kq * 4];
            int b = (4 * kq) * SA + m;
            As[b] = v.x; As[b + SA] = v.y; As[b + 2 * SA] = v.z; As[b + 3 * SA] = v.w;
        }
#pragma unroll
        for (int l = 0; l < 8; l++) {
            int idx = tid + l * 128;
            int r = idx >> 3, kq = idx & 7;
            float4 v1 = *(const float4*)&w1base[(size_t)r * H + kt + kq * 4];
            float4 v3 = *(const float4*)&w3base[(size_t)r * H + kt + kq * 4];
            int b = (4 * kq) * SB + r;
            B1s[b] = v1.x; B1s[b + SB] = v1.y; B1s[b + 2 * SB] = v1.z; B1s[b + 3 * SB] = v1.w;
            B3s[b] = v3.x; B3s[b + SB] = v3.y; B3s[b + 2 * SB] = v3.z; B3s[b + 3 * SB] = v3.w;
        }
        __syncthreads();
#pragma unroll 8
        for (int k = 0; k < 32; k++) {
            float4 a = *(const float4*)&As[k * SA + 4 * ty];
            ull a0 = dup2(a.x), a1 = dup2(a.y), a2 = dup2(a.z), a3 = dup2(a.w);
            const ull* b1 = (const ull*)&B1s[k * SB + 8 * tx];
            const ull* b3 = (const ull*)&B3s[k * SB + 8 * tx];
#pragma unroll
            for (int j = 0; j < 4; j++) {
                ull bv1 = b1[j], bv3 = b3[j];
                fma2(acc1[0][j], a0, bv1); fma2(acc1[1][j], a1, bv1);
                fma2(acc1[2][j], a2, bv1); fma2(acc1[3][j], a3, bv1);
                fma2(acc3[0][j], a0, bv3); fma2(acc3[1][j], a1, bv3);
                fma2(acc3[2][j], a2, bv3); fma2(acc3[3][j], a3, bv3);
            }
        }
        __syncthreads();
    }
#pragma unroll
    for (int mi = 0; mi < 4; mi++) {
        int m = 4 * ty + mi;
        if (m >= mcnt) continue;
        float* outp = g_act + (size_t)slots[m] * IDIM + i0 + 8 * tx;
#pragma unroll
        for (int j = 0; j < 4; j++) {
            float h1a = lo2(acc1[mi][j]), h1b = hi2(acc1[mi][j]);
            float h3a = lo2(acc3[mi][j]), h3b = hi2(acc3[mi][j]);
            outp[2 * j] = silu(h1a) * h3a;
            outp[2 * j + 1] = silu(h1b) * h3b;
        }
    }
}

// ---- stage B: eo = (act_e @ w2_e^T) * combine_weight, per-assignment ----
__global__ __launch_bounds__(128) void stageB_kernel(const float* __restrict__ w2) {
    int e = blockIdx.y;
    int n = g_cnt[e];
    int m0 = blockIdx.z * 32;
    if (m0 >= n) return;
    int h0 = blockIdx.x * 128;
    int tid = threadIdx.x;

    __shared__ float As[32 * SA];
    __shared__ float Bs[32 * SB];
    __shared__ int slots[32];
    __shared__ float wts[32];

    int mcnt = min(32, n - m0);
    if (tid < 32) {
        bool v = tid < mcnt;
        slots[tid] = v ? g_slot[e * T + m0 + tid] : 0;
        wts[tid] = v ? g_wt[e * T + m0 + tid] : 0.0f;
    }
    __syncthreads();

    ull acc[4][4];
#pragma unroll
    for (int a = 0; a < 4; a++)
#pragma unroll
        for (int b = 0; b < 4; b++) acc[a][b] = 0ull;

    int tx = tid & 15, ty = tid >> 4;
    const float* wb = w2 + ((size_t)e * H + h0) * IDIM;

    for (int kt = 0; kt < IDIM; kt += 32) {
#pragma unroll
        for (int l = 0; l < 2; l++) {
            int idx = tid + l * 128;
            int m = idx >> 3, kq = idx & 7;
            float4 v = make_float4(0.f, 0.f, 0.f, 0.f);
            if (m < mcnt) v = *(const float4*)&g_act[(size_t)slots[m] * IDIM + kt + kq * 4];
            int b = (4 * kq) * SA + m;
            As[b] = v.x; As[b + SA] = v.y; As[b + 2 * SA] = v.z; As[b + 3 * SA] = v.w;
        }
#pragma unroll
        for (int l = 0; l < 8; l++) {
            int idx = tid + l * 128;
            int r = idx >> 3, kq = idx & 7;
            float4 v = *(const float4*)&wb[(size_t)r * IDIM + kt + kq * 4];
            int b = (4 * kq) * SB + r;
            Bs[b] = v.x; Bs[b + SB] = v.y; Bs[b + 2 * SB] = v.z; Bs[b + 3 * SB] = v.w;
        }
        __syncthreads();
#pragma unroll 8
        for (int k = 0; k < 32; k++) {
            float4 a = *(const float4*)&As[k * SA + 4 * ty];
            ull a0 = dup2(a.x), a1 = dup2(a.y), a2 = dup2(a.z), a3 = dup2(a.w);
            const ull* bp = (const ull*)&Bs[k * SB + 8 * tx];
#pragma unroll
            for (int j = 0; j < 4; j++) {
                ull bv = bp[j];
                fma2(acc[0][j], a0, bv); fma2(acc[1][j], a1, bv);
                fma2(acc[2][j], a2, bv); fma2(acc[3][j], a3, bv);
            }
        }
        __syncthreads();
    }
#pragma unroll
    for (int mi = 0; mi < 4; mi++) {
        int m = 4 * ty + mi;
        if (m >= mcnt) continue;
        float w = wts[m];
        float* outp = g_eo + (size_t)slots[m] * H + h0 + 8 * tx;
#pragma unroll
        for (int j = 0; j < 4; j++) {
            outp[2 * j] = lo2(acc[mi][j]) * w;
            outp[2 * j + 1] = hi2(acc[mi][j]) * w;
        }
    }
}

// ---- shared expert up: sact = silu(X @ wsg^T) * (X @ wsu^T) ----
__global__ __launch_bounds__(128) void sharedUp_kernel(const float* __restrict__ x,
                                                       const float* __restrict__ wsg,
                                                       const float* __restrict__ wsu) {
    int m0 = blockIdx.y * 32;
    int n0 = blockIdx.x * 128;
    int tid = threadIdx.x;

    __shared__ float As[32 * SA];
    __shared__ float B1s[32 * SB];
    __shared__ float B3s[32 * SB];

    ull acc1[4][4], acc3[4][4];
#pragma unroll
    for (int a = 0; a < 4; a++)
#pragma unroll
        for (int b = 0; b < 4; b++) { acc1[a][b] = 0ull; acc3[a][b] = 0ull; }

    int tx = tid & 15, ty = tid >> 4;
    const float* w1base = wsg + (size_t)n0 * H;
    const float* w3base = wsu + (size_t)n0 * H;

    for (int kt = 0; kt < H; kt += 32) {
#pragma unroll
        for (int l = 0; l < 2; l++) {
            int idx = tid + l * 128;
            int m = idx >> 3, kq = idx & 7;
            float4 v = *(const float4*)&x[(size_t)(m0 + m) * H + kt + kq * 4];
            int b = (4 * kq) * SA + m;
            As[b] = v.x; As[b + SA] = v.y; As[b + 2 * SA] = v.z; As[b + 3 * SA] = v.w;
        }
#pragma unroll
        for (int l = 0; l < 8; l++) {
            int idx = tid + l * 128;
            int r = idx >> 3, kq = idx & 7;
            float4 v1 = *(const float4*)&w1base[(size_t)r * H + kt + kq * 4];
            float4 v3 = *(const float4*)&w3base[(size_t)r * H + kt + kq * 4];
            int b = (4 * kq) * SB + r;
            B1s[b] = v1.x; B1s[b + SB] = v1.y; B1s[b + 2 * SB] = v1.z; B1s[b + 3 * SB] = v1.w;
            B3s[b] = v3.x; B3s[b + SB] = v3.y; B3s[b + 2 * SB] = v3.z; B3s[b + 3 * SB] = v3.w;
        }
        __syncthreads();
#pragma unroll 8
        for (int k = 0; k < 32; k++) {
            float4 a = *(const float4*)&As[k * SA + 4 * ty];
            ull a0 = dup2(a.x), a1 = dup2(a.y), a2 = dup2(a.z), a3 = dup2(a.w);
            const ull* b1 = (const ull*)&B1s[k * SB + 8 * tx];
            const ull* b3 = (const ull*)&B3s[k * SB + 8 * tx];
#pragma unroll
            for (int j = 0; j < 4; j++) {
                ull bv1 = b1[j], bv3 = b3[j];
                fma2(acc1[0][j], a0, bv1); fma2(acc1[1][j], a1, bv1);
                fma2(acc1[2][j], a2, bv1); fma2(acc1[3][j], a3, bv1);
                fma2(acc3[0][j], a0, bv3); fma2(acc3[1][j], a1, bv3);
                fma2(acc3[2][j], a2, bv3); fma2(acc3[3][j], a3, bv3);
            }
        }
        __syncthreads();
    }
#pragma unroll
    for (int mi = 0; mi < 4; mi++) {
        int m = 4 * ty + mi;
        float* outp = g_sact + (size_t)(m0 + m) * SI + n0 + 8 * tx;
#pragma unroll
        for (int j = 0; j < 4; j++) {
            float h1a = lo2(acc1[mi][j]), h1b = hi2(acc1[mi][j]);
            float h3a = lo2(acc3[mi][j]), h3b = hi2(acc3[mi][j]);
            outp[2 * j] = silu(h1a) * h3a;
            outp[2 * j + 1] = silu(h1b) * h3b;
        }
    }
}

// ---- shared expert down: out = sact @ wsd^T (writes d_out directly) ----
__global__ __launch_bounds__(128) void sharedDown_kernel(const float* __restrict__ wsd,
                                                         float* __restrict__ out) {
    int m0 = blockIdx.y * 32;
    int h0 = blockIdx.x * 128;
    int tid = threadIdx.x;

    __shared__ float As[32 * SA];
    __shared__ float Bs[32 * SB];

    ull acc[4][4];
#pragma unroll
    for (int a = 0; a < 4; a++)
#pragma unroll
        for (int b = 0; b < 4; b++) acc[a][b] = 0ull;

    int tx = tid & 15, ty = tid >> 4;
    const float* wb = wsd + (size_t)h0 * SI;

    for (int kt = 0; kt < SI; kt += 32) {
#pragma unroll
        for (int l = 0; l < 2; l++) {
            int idx = tid + l * 128;
            int m = idx >> 3, kq = idx & 7;
            float4 v = *(const float4*)&g_sact[(size_t)(m0 + m) * SI + kt + kq * 4];
            int b = (4 * kq) * SA + m;
            As[b] = v.x; As[b + SA] = v.y; As[b + 2 * SA] = v.z; As[b + 3 * SA] = v.w;
        }
#pragma unroll
        for (int l = 0; l < 8; l++) {
            int idx = tid + l * 128;
            int r = idx >> 3, kq = idx & 7;
            float4 v = *(const float4*)&wb[(size_t)r * SI + kt + kq * 4];
            int b = (4 * kq) * SB + r;
            Bs[b] = v.x; Bs[b + SB] = v.y; Bs[b + 2 * SB] = v.z; Bs[b + 3 * SB] = v.w;
        }
        __syncthreads();
#pragma unroll 8
        for (int k = 0; k < 32; k++) {
            float4 a = *(const float4*)&As[k * SA + 4 * ty];
            ull a0 = dup2(a.x), a1 = dup2(a.y), a2 = dup2(a.z), a3 = dup2(a.w);
            const ull* bp = (const ull*)&Bs[k * SB + 8 * tx];
#pragma unroll
            for (int j = 0; j < 4; j++) {
                ull bv = bp[j];
                fma2(acc[0][j], a0, bv); fma2(acc[1][j], a1, bv);
                fma2(acc[2][j], a2, bv); fma2(acc[3][j], a3, bv);
            }
        }
        __syncthreads();
    }
#pragma unroll
    for (int mi = 0; mi < 4; mi++) {
        int m = 4 * ty + mi;
        float* outp = out + (size_t)(m0 + m) * H + h0 + 8 * tx;
#pragma unroll
        for (int j = 0; j < 4; j++) {
            outp[2 * j] = lo2(acc[mi][j]);
            outp[2 * j + 1] = hi2(acc[mi][j]);
        }
    }
}

// ---- combine: out += sum over the 6 weighted expert outputs of each token ----
__global__ void combine_kernel(float* __restrict__ out) {
    int idx = blockIdx.x * 256 + threadIdx.x;  // T*H total
    int t = idx >> 10;
    int h = idx & 1023;
    float s = out[idx];
#pragma unroll
    for (int k = 0; k < TOPK; k++)
        s += g_eo[((size_t)(t * TOPK + k) << 10) + h];
    out[idx] = s;
}

// ---------------- launch ----------------
extern "C" void kernel_launch(void* const* d_in, const int* in_sizes, int n_in,
                              void* d_out, int out_size) {
    const float* x     = (const float*)d_in[0];
    const float* gw    = (const float*)d_in[1];
    const float* ebias = (const float*)d_in[2];
    const float* w1    = (const float*)d_in[3];
    const float* w3    = (const float*)d_in[4];
    const float* w2    = (const float*)d_in[5];
    const float* wsg   = (const float*)d_in[6];
    const float* wsu   = (const float*)d_in[7];
    const float* wsd   = (const float*)d_in[8];
    float* out = (float*)d_out;

    init_kernel<<<1, 64>>>();
    gate_routing_kernel<<<T, 256>>>(x, gw, ebias);
    stageA_kernel<<<dim3(IDIM / 128, E, T / 32), 128>>>(x, w1, w3);
    stageB_kernel<<<dim3(H / 128, E, T / 32), 128>>>(w2);
    sharedUp_kernel<<<dim3(SI / 128, T / 32), 128>>>(x, wsg, wsu);
    sharedDown_kernel<<<dim3(H / 128, T / 32), 128>>>(wsd, out);
    combine_kernel<<<(T * H) / 256, 256>>>(out);
}

// round 2
// speedup vs baseline: 3.1082x; 3.1082x over previous
#include <cuda_runtime.h>
#include <cuda_bf16.h>

#define T 256
#define H 1024
#define E 64
#define IDIM 512
#define SI 2048
#define TOPK 6

// ---------------- device scratch ----------------
__device__ int   g_cnt[E];
__device__ int   g_slot[E * T];
__device__ int   g_tok[E * T];
__device__ float g_wt[E * T];
__device__ float g_act[T * TOPK * IDIM];   // 3 MB
__device__ float g_eo[T * TOPK * H];       // 6 MB
__device__ float g_sact[T * SI];           // 2 MB

__device__ __forceinline__ float silu(float v) { return v / (1.0f + expf(-v)); }

// ---------------- init ----------------
__global__ void init_kernel() {
    if (threadIdx.x < E) g_cnt[threadIdx.x] = 0;
}

// ---------------- gate + routing: one block per token ----------------
__global__ void gate_routing_kernel(const float* __restrict__ x,
                                    const float* __restrict__ gw,
                                    const float* __restrict__ ebias) {
    __shared__ float xs[H];
    __shared__ float part[256];
    __shared__ float logits[E];
    int t = blockIdx.x, tid = threadIdx.x;

    ((float4*)xs)[tid] = ((const float4*)(x + (size_t)t * H))[tid];
    __syncthreads();

    int e = tid >> 2, q = tid & 3;
    const float* gr = gw + (size_t)e * H + q * 256;
    const float* xr = xs + q * 256;
    float s = 0.0f;
#pragma unroll 8
    for (int k = 0; k < 256; k += 4) {
        float4 g = *(const float4*)(gr + k);
        float4 xv = *(const float4*)(xr + k);
        s += g.x * xv.x + g.y * xv.y + g.z * xv.z + g.w * xv.w;
    }
    part[tid] = s;
    __syncthreads();
    if (tid < E) logits[tid] = part[tid * 4] + part[tid * 4 + 1] + part[tid * 4 + 2] + part[tid * 4 + 3];
    __syncthreads();

    if (tid == 0) {
        float sc[E], swb[E];
        for (int i = 0; i < E; i++) {
            float l = logits[i];
            sc[i] = 1.0f / (1.0f + expf(-l));
            swb[i] = sc[i] + ebias[i];
        }
        float gs[8];
        for (int g = 0; g < 8; g++) {
            float m1 = -1e30f, m2 = -1e30f;
            for (int j = 0; j < 8; j++) {
                float v = swb[g * 8 + j];
                if (v > m1) { m2 = m1; m1 = v; }
                else if (v > m2) { m2 = v; }
            }
            gs[g] = m1 + m2;
        }
        bool gsel[8];
        for (int g = 0; g < 8; g++) gsel[g] = false;
        for (int r = 0; r < 4; r++) {
            int best = 0; float bv = -1e30f;
            for (int g = 0; g < 8; g++)
                if (!gsel[g] && gs[g] > bv) { bv = gs[g]; best = g; }
            gsel[best] = true;
        }
        bool picked[E];
        for (int i = 0; i < E; i++) picked[i] = false;
        int idx[TOPK];
        float wsum = 0.0f;
        for (int r = 0; r < TOPK; r++) {
            int best = 0; float bv = -1e30f;
            for (int i = 0; i < E; i++) {
                if (picked[i]) continue;
                float v = gsel[i >> 3] ? swb[i] : 0.0f;
                if (v > bv) { bv = v; best = i; }
            }
            picked[best] = true;
            idx[r] = best;
            wsum += sc[best];
        }
        float inv = 2.5f / (wsum + 1e-20f);
        for (int r = 0; r < TOPK; r++) {
            int ee = idx[r];
            int pos = atomicAdd(&g_cnt[ee], 1);
            g_slot[ee * T + pos] = t * TOPK + r;
            g_tok[ee * T + pos] = t;
            g_wt[ee * T + pos] = sc[ee] * inv;
        }
    }
}

// ================= unified bf16-split MMA GEMM =================
// C[M=32, N=64] = A[32, KD] * B[N, KD]^T, fp32 in HBM, converted to bf16
// hi/lo in-register, 3-term MMA (hi*hi + hi*lo + lo*hi) for fp32 accuracy.
// 128 threads = 4 warps: warp (wm, wn) handles m16 x n32.
// smem bf16 rows padded to stride 40 elems (80B) -> conflict-free ldmatrix.

__device__ __forceinline__ void ldsm4(unsigned r[4], unsigned addr) {
    asm volatile("ldmatrix.sync.aligned.m8n8.x4.shared.b16 {%0,%1,%2,%3}, [%4];"
        : "=r"(r[0]), "=r"(r[1]), "=r"(r[2]), "=r"(r[3]) : "r"(addr));
}

__device__ __forceinline__ void mma_bf16(float c[4], const unsigned a[4],
                                         unsigned b0, unsigned b1) {
    asm volatile("mma.sync.aligned.m16n8k16.row.col.f32.bf16.bf16.f32 "
        "{%0,%1,%2,%3}, {%4,%5,%6,%7}, {%8,%9}, {%0,%1,%2,%3};"
        : "+f"(c[0]), "+f"(c[1]), "+f"(c[2]), "+f"(c[3])
        : "r"(a[0]), "r"(a[1]), "r"(a[2]), "r"(a[3]), "r"(b0), "r"(b1));
}

__device__ __forceinline__ void cvt_store(float4 v, __nv_bfloat16* hi, __nv_bfloat16* lo) {
    __nv_bfloat162 h01 = __floats2bfloat162_rn(v.x, v.y);
    __nv_bfloat162 h23 = __floats2bfloat162_rn(v.z, v.w);
    float2 f01 = __bfloat1622float2(h01);
    float2 f23 = __bfloat1622float2(h23);
    *(__nv_bfloat162*)hi       = h01;
    *(__nv_bfloat162*)(hi + 2) = h23;
    *(__nv_bfloat162*)lo       = __floats2bfloat162_rn(v.x - f01.x, v.y - f01.y);
    *(__nv_bfloat162*)(lo + 2) = __floats2bfloat162_rn(v.z - f23.x, v.w - f23.y);
}

// EPI: 0 = silu(acc0)*acc1   1 = acc0 * combine_weight   2 = plain acc0
// GATHER: expert lists via blockIdx.y/z; else blockIdx.y = m-tile
// ATOK: gathered A row index = g_tok (else g_slot)
// ASRC: 0 = Ain param, 1 = g_act, 2 = g_sact
// ODST: 0 = Oout param, 1 = g_act, 2 = g_eo, 3 = g_sact
template<int KD, bool TWOB, int EPI, bool GATHER, bool ATOK, int ASRC, int ODST>
__global__ __launch_bounds__(128) void mma_gemm(
    const float* __restrict__ Ain, const float* __restrict__ B1in,
    const float* __restrict__ B2in, float* __restrict__ Oout,
    int ostride, long estrideB)
{
    constexpr int NB = TWOB ? 2 : 1;
    constexpr int NCH = KD / 32;

    const float* A = (ASRC == 0) ? Ain : (ASRC == 1) ? (const float*)g_act : (const float*)g_sact;
    float* O = (ODST == 0) ? Oout : (ODST == 1) ? g_act : (ODST == 2) ? g_eo : g_sact;

    int tid = threadIdx.x, lane = tid & 31, wid = tid >> 5;
    int wm = wid & 1, wn = wid >> 1;
    int n0 = blockIdx.x * 64;

    __shared__ int s_row[32];
    __shared__ int s_orow[32];
    __shared__ float s_wt[32];
    __shared__ __align__(16) __nv_bfloat16 sA[2][32 * 40];
    __shared__ __align__(16) __nv_bfloat16 sB[NB][2][64 * 40];

    int mcnt = 32;
    const float* Bp[NB];
    if (GATHER) {
        int e = blockIdx.y;
        int n = g_cnt[e];
        int m0 = blockIdx.z * 32;
        if (m0 >= n) return;
        mcnt = min(32, n - m0);
        if (tid < 32) {
            bool v = tid < mcnt;
            int idx = e * T + m0 + tid;
            s_row[tid]  = v ? (ATOK ? g_tok[idx] : g_slot[idx]) : -1;
            s_orow[tid] = v ? g_slot[idx] : 0;
            s_wt[tid]   = v ? g_wt[idx] : 0.0f;
        }
        Bp[0] = B1in + (size_t)e * estrideB + (size_t)n0 * KD;
        if (TWOB) Bp[1] = B2in + (size_t)e * estrideB + (size_t)n0 * KD;
    } else {
        int m0 = blockIdx.y * 32;
        if (tid < 32) { s_row[tid] = m0 + tid; s_orow[tid] = m0 + tid; }
        Bp[0] = B1in + (size_t)n0 * KD;
        if (TWOB) Bp[1] = B2in + (size_t)n0 * KD;
    }
    __syncthreads();

    // load-lane mapping
    int ar = tid >> 2, ac = (tid & 3) * 2;   // A: row ar, float4 cols ac, ac+1
    int br = tid >> 1, bc = (tid & 1) * 4;   // B: row br, float4 cols bc..bc+3
    long aoff = (long)s_row[ar];

    float4 pa[2];
    float4 pb[NB][4];

    auto load_chunk = [&](int kt) {
#pragma unroll
        for (int i = 0; i < 2; i++) {
            if (!GATHER || aoff >= 0)
                pa[i] = *(const float4*)&A[(size_t)aoff * KD + kt + (ac + i) * 4];
            else
                pa[i] = make_float4(0.f, 0.f, 0.f, 0.f);
        }
#pragma unroll
        for (int m = 0; m < NB; m++)
#pragma unroll
            for (int i = 0; i < 4; i++)
                pb[m][i] = *(const float4*)&Bp[m][(size_t)br * KD + kt + (bc + i) * 4];
    };

    auto store_chunk = [&]() {
#pragma unroll
        for (int i = 0; i < 2; i++)
            cvt_store(pa[i], &sA[0][ar * 40 + (ac + i) * 4], &sA[1][ar * 40 + (ac + i) * 4]);
#pragma unroll
        for (int m = 0; m < NB; m++)
#pragma unroll
            for (int i = 0; i < 4; i++)
                cvt_store(pb[m][i], &sB[m][0][br * 40 + (bc + i) * 4],
                                    &sB[m][1][br * 40 + (bc + i) * 4]);
    };

    float acc[NB][4][4];
#pragma unroll
    for (int m = 0; m < NB; m++)
#pragma unroll
        for (int nt = 0; nt < 4; nt++)
#pragma unroll
            for (int j = 0; j < 4; j++) acc[m][nt][j] = 0.0f;

    unsigned aBaseHi = (unsigned)__cvta_generic_to_shared(&sA[0][0]);
    unsigned aBaseLo = (unsigned)__cvta_generic_to_shared(&sA[1][0]);
    int arow_off = ((wm * 16 + (lane & 15)) * 40 + ((lane >> 4) & 1) * 8) * 2;
    int brow_base = wn * 32 + (lane & 7) + ((lane & 16) >> 1);
    int bcol_off = (lane & 8);

    load_chunk(0);
    for (int ch = 0; ch < NCH; ch++) {
        store_chunk();
        __syncthreads();
        if (ch + 1 < NCH) load_chunk((ch + 1) * 32);

#pragma unroll
        for (int s = 0; s < 2; s++) {
            unsigned ah[4], al[4];
            ldsm4(ah, aBaseHi + arow_off + s * 32);
            ldsm4(al, aBaseLo + arow_off + s * 32);
#pragma unroll
            for (int m = 0; m < NB; m++) {
                unsigned bHi = (unsigned)__cvta_generic_to_shared(&sB[m][0][0]);
                unsigned bLo = (unsigned)__cvta_generic_to_shared(&sB[m][1][0]);
                int o0 = (brow_base * 40 + s * 16 + bcol_off) * 2;
                int o1 = ((brow_base + 16) * 40 + s * 16 + bcol_off) * 2;
                unsigned bh[8], bl[8];
                ldsm4(bh, bHi + o0); ldsm4(bh + 4, bHi + o1);
                ldsm4(bl, bLo + o0); ldsm4(bl + 4, bLo + o1);
#pragma unroll
                for (int nt = 0; nt < 4; nt++) {
                    mma_bf16(acc[m][nt], ah, bh[nt * 2], bh[nt * 2 + 1]);
                    mma_bf16(acc[m][nt], ah, bl[nt * 2], bl[nt * 2 + 1]);
                    mma_bf16(acc[m][nt], al, bh[nt * 2], bh[nt * 2 + 1]);
                }
            }
        }
        __syncthreads();
    }

    // epilogue
    int g = lane >> 2, tq = lane & 3;
#pragma unroll
    for (int half = 0; half < 2; half++) {
        int m = wm * 16 + g + half * 8;
        if (m >= mcnt) continue;
        float w = (EPI == 1) ? s_wt[m] : 0.0f;
        float* op = O + (size_t)s_orow[m] * ostride + n0 + wn * 32 + 2 * tq;
#pragma unroll
        for (int nt = 0; nt < 4; nt++) {
            float v0, v1;
            if (EPI == 0) {
                v0 = silu(acc[0][nt][half * 2])     * acc[1][nt][half * 2];
                v1 = silu(acc[0][nt][half * 2 + 1]) * acc[1][nt][half * 2 + 1];
            } else if (EPI == 1) {
                v0 = acc[0][nt][half * 2] * w;
                v1 = acc[0][nt][half * 2 + 1] * w;
            } else {
                v0 = acc[0][nt][half * 2];
                v1 = acc[0][nt][half * 2 + 1];
            }
            *(float2*)&op[nt * 8] = make_float2(v0, v1);
        }
    }
}

// ---- combine: out += sum of the 6 weighted expert outputs per token ----
__global__ void combine_kernel(float* __restrict__ out) {
    int idx = blockIdx.x * 256 + threadIdx.x;
    int t = idx >> 10;
    int h = idx & 1023;
    float s = out[idx];
#pragma unroll
    for (int k = 0; k < TOPK; k++)
        s += g_eo[((size_t)(t * TOPK + k) << 10) + h];
    out[idx] = s;
}

// ---------------- launch ----------------
extern "C" void kernel_launch(void* const* d_in, const int* in_sizes, int n_in,
                              void* d_out, int out_size) {
    const float* x     = (const float*)d_in[0];
    const float* gw    = (const float*)d_in[1];
    const float* ebias = (const float*)d_in[2];
    const float* w1    = (const float*)d_in[3];
    const float* w3    = (const float*)d_in[4];
    const float* w2    = (const float*)d_in[5];
    const float* wsg   = (const float*)d_in[6];
    const float* wsu   = (const float*)d_in[7];
    const float* wsd   = (const float*)d_in[8];
    float* out = (float*)d_out;

    init_kernel<<<1, 64>>>();
    gate_routing_kernel<<<T, 256>>>(x, gw, ebias);

    // stage A: act = silu(x_e @ w1^T) * (x_e @ w3^T)   [gather tokens]
    mma_gemm<1024, true, 0, true, true, 0, 1>
        <<<dim3(IDIM / 64, E, T / 32), 128>>>(x, w1, w3, nullptr, IDIM, (long)IDIM * H);
    // stage B: eo = (act_e @ w2^T) * cw                 [gather slots]
    mma_gemm<512, false, 1, true, false, 1, 2>
        <<<dim3(H / 64, E, T / 32), 128>>>(nullptr, w2, w2, nullptr, H, (long)H * IDIM);
    // shared up: sact = silu(x @ wsg^T) * (x @ wsu^T)
    mma_gemm<1024, true, 0, false, false, 0, 3>
        <<<dim3(SI / 64, T / 32), 128>>>(x, wsg, wsu, nullptr, SI, 0);
    // shared down: out = sact @ wsd^T
    mma_gemm<2048, false, 2, false, false, 2, 0>
        <<<dim3(H / 64, T / 32), 128>>>(nullptr, wsd, wsd, out, H, 0);

    combine_kernel<<<(T * H) / 256, 256>>>(out);
}

// round 3
// speedup vs baseline: 3.1118x; 1.0012x over previous
#include <cuda_runtime.h>
#include <cuda_bf16.h>

#define T 256
#define H 1024
#define E 64
#define IDIM 512
#define SI 2048
#define TOPK 6

// ---------------- device scratch ----------------
__device__ int   g_cnt[E];
__device__ int   g_slot[E * T];
__device__ int   g_tok[E * T];
__device__ float g_wt[E * T];
__device__ float g_act[T * TOPK * IDIM];   // 3 MB
__device__ float g_eo[T * TOPK * H];       // 6 MB
__device__ float g_sact[T * SI];           // 2 MB

__device__ __forceinline__ float silu(float v) { return v / (1.0f + expf(-v)); }

// ---------------- init ----------------
__global__ void init_kernel() {
    if (threadIdx.x < E) g_cnt[threadIdx.x] = 0;
}

// ---------------- gate + routing: one block per token ----------------
__global__ void gate_routing_kernel(const float* __restrict__ x,
                                    const float* __restrict__ gw,
                                    const float* __restrict__ ebias) {
    __shared__ float xs[H];
    __shared__ float part[256];
    __shared__ float logits[E];
    int t = blockIdx.x, tid = threadIdx.x;

    ((float4*)xs)[tid] = ((const float4*)(x + (size_t)t * H))[tid];
    __syncthreads();

    int e = tid >> 2, q = tid & 3;
    const float* gr = gw + (size_t)e * H + q * 256;
    const float* xr = xs + q * 256;
    float s = 0.0f;
#pragma unroll 8
    for (int k = 0; k < 256; k += 4) {
        float4 g = *(const float4*)(gr + k);
        float4 xv = *(const float4*)(xr + k);
        s += g.x * xv.x + g.y * xv.y + g.z * xv.z + g.w * xv.w;
    }
    part[tid] = s;
    __syncthreads();
    if (tid < E) logits[tid] = part[tid * 4] + part[tid * 4 + 1] + part[tid * 4 + 2] + part[tid * 4 + 3];
    __syncthreads();

    if (tid == 0) {
        float sc[E], swb[E];
        for (int i = 0; i < E; i++) {
            float l = logits[i];
            sc[i] = 1.0f / (1.0f + expf(-l));
            swb[i] = sc[i] + ebias[i];
        }
        float gs[8];
        for (int g = 0; g < 8; g++) {
            float m1 = -1e30f, m2 = -1e30f;
            for (int j = 0; j < 8; j++) {
                float v = swb[g * 8 + j];
                if (v > m1) { m2 = m1; m1 = v; }
                else if (v > m2) { m2 = v; }
            }
            gs[g] = m1 + m2;
        }
        bool gsel[8];
        for (int g = 0; g < 8; g++) gsel[g] = false;
        for (int r = 0; r < 4; r++) {
            int best = 0; float bv = -1e30f;
            for (int g = 0; g < 8; g++)
                if (!gsel[g] && gs[g] > bv) { bv = gs[g]; best = g; }
            gsel[best] = true;
        }
        bool picked[E];
        for (int i = 0; i < E; i++) picked[i] = false;
        int idx[TOPK];
        float wsum = 0.0f;
        for (int r = 0; r < TOPK; r++) {
            int best = 0; float bv = -1e30f;
            for (int i = 0; i < E; i++) {
                if (picked[i]) continue;
                float v = gsel[i >> 3] ? swb[i] : 0.0f;
                if (v > bv) { bv = v; best = i; }
            }
            picked[best] = true;
            idx[r] = best;
            wsum += sc[best];
        }
        float inv = 2.5f / (wsum + 1e-20f);
        for (int r = 0; r < TOPK; r++) {
            int ee = idx[r];
            int pos = atomicAdd(&g_cnt[ee], 1);
            g_slot[ee * T + pos] = t * TOPK + r;
            g_tok[ee * T + pos] = t;
            g_wt[ee * T + pos] = sc[ee] * inv;
        }
    }
}

// ================= unified bf16-split MMA GEMM =================
// C[M=32, N=64] = A[32, KD] * B[N, KD]^T, fp32 in HBM, converted to bf16
// hi/lo in-register, 3-term MMA (hi*hi + hi*lo + lo*hi) for fp32 accuracy.
// 128 threads = 4 warps: warp (wm, wn) handles m16 x n32.
// smem bf16 rows padded to stride 40 elems (80B) -> conflict-free ldmatrix.

__device__ __forceinline__ void ldsm4(unsigned r[4], unsigned addr) {
    asm volatile("ldmatrix.sync.aligned.m8n8.x4.shared.b16 {%0,%1,%2,%3}, [%4];"
        : "=r"(r[0]), "=r"(r[1]), "=r"(r[2]), "=r"(r[3]) : "r"(addr));
}

__device__ __forceinline__ void mma_bf16(float c[4], const unsigned a[4],
                                         unsigned b0, unsigned b1) {
    asm volatile("mma.sync.aligned.m16n8k16.row.col.f32.bf16.bf16.f32 "
        "{%0,%1,%2,%3}, {%4,%5,%6,%7}, {%8,%9}, {%0,%1,%2,%3};"
        : "+f"(c[0]), "+f"(c[1]), "+f"(c[2]), "+f"(c[3])
        : "r"(a[0]), "r"(a[1]), "r"(a[2]), "r"(a[3]), "r"(b0), "r"(b1));
}

__device__ __forceinline__ void cvt_store(float4 v, __nv_bfloat16* hi, __nv_bfloat16* lo) {
    __nv_bfloat162 h01 = __floats2bfloat162_rn(v.x, v.y);
    __nv_bfloat162 h23 = __floats2bfloat162_rn(v.z, v.w);
    float2 f01 = __bfloat1622float2(h01);
    float2 f23 = __bfloat1622float2(h23);
    *(__nv_bfloat162*)hi       = h01;
    *(__nv_bfloat162*)(hi + 2) = h23;
    *(__nv_bfloat162*)lo       = __floats2bfloat162_rn(v.x - f01.x, v.y - f01.y);
    *(__nv_bfloat162*)(lo + 2) = __floats2bfloat162_rn(v.z - f23.x, v.w - f23.y);
}

// EPI: 0 = silu(acc0)*acc1   1 = acc0 * combine_weight   2 = plain acc0
// GATHER: expert lists via blockIdx.y/z; else blockIdx.y = m-tile
// ATOK: gathered A row index = g_tok (else g_slot)
// ASRC: 0 = Ain param, 1 = g_act, 2 = g_sact
// ODST: 0 = Oout param, 1 = g_act, 2 = g_eo, 3 = g_sact
template<int KD, bool TWOB, int EPI, bool GATHER, bool ATOK, int ASRC, int ODST>
__global__ __launch_bounds__(128) void mma_gemm(
    const float* __restrict__ Ain, const float* __restrict__ B1in,
    const float* __restrict__ B2in, float* __restrict__ Oout,
    int ostride, long estrideB)
{
    constexpr int NB = TWOB ? 2 : 1;
    constexpr int NCH = KD / 32;

    const float* A = (ASRC == 0) ? Ain : (ASRC == 1) ? (const float*)g_act : (const float*)g_sact;
    float* O = (ODST == 0) ? Oout : (ODST == 1) ? g_act : (ODST == 2) ? g_eo : g_sact;

    int tid = threadIdx.x, lane = tid & 31, wid = tid >> 5;
    int wm = wid & 1, wn = wid >> 1;
    int n0 = blockIdx.x * 64;

    __shared__ int s_row[32];
    __shared__ int s_orow[32];
    __shared__ float s_wt[32];
    __shared__ __align__(16) __nv_bfloat16 sA[2][32 * 40];
    __shared__ __align__(16) __nv_bfloat16 sB[NB][2][64 * 40];

    int mcnt = 32;
    const float* Bp[NB];
    if (GATHER) {
        int e = blockIdx.y;
        int n = g_cnt[e];
        int m0 = blockIdx.z * 32;
        if (m0 >= n) return;
        mcnt = min(32, n - m0);
        if (tid < 32) {
            bool v = tid < mcnt;
            int idx = e * T + m0 + tid;
            s_row[tid]  = v ? (ATOK ? g_tok[idx] : g_slot[idx]) : -1;
            s_orow[tid] = v ? g_slot[idx] : 0;
            s_wt[tid]   = v ? g_wt[idx] : 0.0f;
        }
        Bp[0] = B1in + (size_t)e * estrideB + (size_t)n0 * KD;
        if (TWOB) Bp[1] = B2in + (size_t)e * estrideB + (size_t)n0 * KD;
    } else {
        int m0 = blockIdx.y * 32;
        if (tid < 32) { s_row[tid] = m0 + tid; s_orow[tid] = m0 + tid; }
        Bp[0] = B1in + (size_t)n0 * KD;
        if (TWOB) Bp[1] = B2in + (size_t)n0 * KD;
    }
    __syncthreads();

    // load-lane mapping
    int ar = tid >> 2, ac = (tid & 3) * 2;   // A: row ar, float4 cols ac, ac+1
    int br = tid >> 1, bc = (tid & 1) * 4;   // B: row br, float4 cols bc..bc+3
    long aoff = (long)s_row[ar];

    float4 pa[2];
    float4 pb[NB][4];

    auto load_chunk = [&](int kt) {
#pragma unroll
        for (int i = 0; i < 2; i++) {
            if (!GATHER || aoff >= 0)
                pa[i] = *(const float4*)&A[(size_t)aoff * KD + kt + (ac + i) * 4];
            else
                pa[i] = make_float4(0.f, 0.f, 0.f, 0.f);
        }
#pragma unroll
        for (int m = 0; m < NB; m++)
#pragma unroll
            for (int i = 0; i < 4; i++)
                pb[m][i] = *(const float4*)&Bp[m][(size_t)br * KD + kt + (bc + i) * 4];
    };

    auto store_chunk = [&]() {
#pragma unroll
        for (int i = 0; i < 2; i++)
            cvt_store(pa[i], &sA[0][ar * 40 + (ac + i) * 4], &sA[1][ar * 40 + (ac + i) * 4]);
#pragma unroll
        for (int m = 0; m < NB; m++)
#pragma unroll
            for (int i = 0; i < 4; i++)
                cvt_store(pb[m][i], &sB[m][0][br * 40 + (bc + i) * 4],
                                    &sB[m][1][br * 40 + (bc + i) * 4]);
    };

    float acc[NB][4][4];
#pragma unroll
    for (int m = 0; m < NB; m++)
#pragma unroll
        for (int nt = 0; nt < 4; nt++)
#pragma unroll
            for (int j = 0; j < 4; j++) acc[m][nt][j] = 0.0f;

    unsigned aBaseHi = (unsigned)__cvta_generic_to_shared(&sA[0][0]);
    unsigned aBaseLo = (unsigned)__cvta_generic_to_shared(&sA[1][0]);
    int arow_off = ((wm * 16 + (lane & 15)) * 40 + ((lane >> 4) & 1) * 8) * 2;
    int brow_base = wn * 32 + (lane & 7) + ((lane & 16) >> 1);
    int bcol_off = (lane & 8);

    load_chunk(0);
    for (int ch = 0; ch < NCH; ch++) {
        store_chunk();
        __syncthreads();
        if (ch + 1 < NCH) load_chunk((ch + 1) * 32);

#pragma unroll
        for (int s = 0; s < 2; s++) {
            unsigned ah[4], al[4];
            ldsm4(ah, aBaseHi + arow_off + s * 32);
            ldsm4(al, aBaseLo + arow_off + s * 32);
#pragma unroll
            for (int m = 0; m < NB; m++) {
                unsigned bHi = (unsigned)__cvta_generic_to_shared(&sB[m][0][0]);
                unsigned bLo = (unsigned)__cvta_generic_to_shared(&sB[m][1][0]);
                int o0 = (brow_base * 40 + s * 16 + bcol_off) * 2;
                int o1 = ((brow_base + 16) * 40 + s * 16 + bcol_off) * 2;
                unsigned bh[8], bl[8];
                ldsm4(bh, bHi + o0); ldsm4(bh + 4, bHi + o1);
                ldsm4(bl, bLo + o0); ldsm4(bl + 4, bLo + o1);
#pragma unroll
                for (int nt = 0; nt < 4; nt++) {
                    mma_bf16(acc[m][nt], ah, bh[nt * 2], bh[nt * 2 + 1]);
                    mma_bf16(acc[m][nt], ah, bl[nt * 2], bl[nt * 2 + 1]);
                    mma_bf16(acc[m][nt], al, bh[nt * 2], bh[nt * 2 + 1]);
                }
            }
        }
        __syncthreads();
    }

    // epilogue
    int g = lane >> 2, tq = lane & 3;
#pragma unroll
    for (int half = 0; half < 2; half++) {
        int m = wm * 16 + g + half * 8;
        if (m >= mcnt) continue;
        float w = (EPI == 1) ? s_wt[m] : 0.0f;
        float* op = O + (size_t)s_orow[m] * ostride + n0 + wn * 32 + 2 * tq;
#pragma unroll
        for (int nt = 0; nt < 4; nt++) {
            float v0, v1;
            if (EPI == 0) {
                v0 = silu(acc[0][nt][half * 2])     * acc[1][nt][half * 2];
                v1 = silu(acc[0][nt][half * 2 + 1]) * acc[1][nt][half * 2 + 1];
            } else if (EPI == 1) {
                v0 = acc[0][nt][half * 2] * w;
                v1 = acc[0][nt][half * 2 + 1] * w;
            } else {
                v0 = acc[0][nt][half * 2];
                v1 = acc[0][nt][half * 2 + 1];
            }
            *(float2*)&op[nt * 8] = make_float2(v0, v1);
        }
    }
}

// ---- combine: out += sum of the 6 weighted expert outputs per token ----
__global__ void combine_kernel(float* __restrict__ out) {
    int idx = blockIdx.x * 256 + threadIdx.x;
    int t = idx >> 10;
    int h = idx & 1023;
    float s = out[idx];
#pragma unroll
    for (int k = 0; k < TOPK; k++)
        s += g_eo[((size_t)(t * TOPK + k) << 10) + h];
    out[idx] = s;
}

// ---------------- launch ----------------
extern "C" void kernel_launch(void* const* d_in, const int* in_sizes, int n_in,
                              void* d_out, int out_size) {
    const float* x     = (const float*)d_in[0];
    const float* gw    = (const float*)d_in[1];
    const float* ebias = (const float*)d_in[2];
    const float* w1    = (const float*)d_in[3];
    const float* w3    = (const float*)d_in[4];
    const float* w2    = (const float*)d_in[5];
    const float* wsg   = (const float*)d_in[6];
    const float* wsu   = (const float*)d_in[7];
    const float* wsd   = (const float*)d_in[8];
    float* out = (float*)d_out;

    init_kernel<<<1, 64>>>();
    gate_routing_kernel<<<T, 256>>>(x, gw, ebias);

    // stage A: act = silu(x_e @ w1^T) * (x_e @ w3^T)   [gather tokens]
    mma_gemm<1024, true, 0, true, true, 0, 1>
        <<<dim3(IDIM / 64, E, T / 32), 128>>>(x, w1, w3, nullptr, IDIM, (long)IDIM * H);
    // stage B: eo = (act_e @ w2^T) * cw                 [gather slots]
    mma_gemm<512, false, 1, true, false, 1, 2>
        <<<dim3(H / 64, E, T / 32), 128>>>(nullptr, w2, w2, nullptr, H, (long)H * IDIM);
    // shared up: sact = silu(x @ wsg^T) * (x @ wsu^T)
    mma_gemm<1024, true, 0, false, false, 0, 3>
        <<<dim3(SI / 64, T / 32), 128>>>(x, wsg, wsu, nullptr, SI, 0);
    // shared down: out = sact @ wsd^T
    mma_gemm<2048, false, 2, false, false, 2, 0>
        <<<dim3(H / 64, T / 32), 128>>>(nullptr, wsd, wsd, out, H, 0);

    combine_kernel<<<(T * H) / 256, 256>>>(out);
}

// round 4
// speedup vs baseline: 3.1298x; 1.0058x over previous
#include <cuda_runtime.h>
#include <cuda_bf16.h>

#define T 256
#define H 1024
#define E 64
#define IDIM 512
#define SI 2048
#define TOPK 6

// ---------------- device scratch ----------------
__device__ int   g_cnt[E];
__device__ int   g_slot[E * T];
__device__ int   g_tok[E * T];
__device__ float g_wt[E * T];
__device__ float g_act[T * TOPK * IDIM];   // 3 MB
__device__ float g_eo[T * TOPK * H];       // 6 MB
__device__ float g_sact[T * SI];           // 2 MB

__device__ __forceinline__ float silu(float v) { return v / (1.0f + expf(-v)); }

// ---------------- init ----------------
__global__ void init_kernel() {
    if (threadIdx.x < E) g_cnt[threadIdx.x] = 0;
}

// ---------------- gate + routing: one block per token ----------------
__global__ void gate_routing_kernel(const float* __restrict__ x,
                                    const float* __restrict__ gw,
                                    const float* __restrict__ ebias) {
    __shared__ float xs[H];
    __shared__ float part[256];
    __shared__ float logits[E];
    int t = blockIdx.x, tid = threadIdx.x;

    ((float4*)xs)[tid] = ((const float4*)(x + (size_t)t * H))[tid];
    __syncthreads();

    int e = tid >> 2, q = tid & 3;
    const float* gr = gw + (size_t)e * H + q * 256;
    const float* xr = xs + q * 256;
    float s = 0.0f;
#pragma unroll 8
    for (int k = 0; k < 256; k += 4) {
        float4 g = *(const float4*)(gr + k);
        float4 xv = *(const float4*)(xr + k);
        s += g.x * xv.x + g.y * xv.y + g.z * xv.z + g.w * xv.w;
    }
    part[tid] = s;
    __syncthreads();
    if (tid < E) logits[tid] = part[tid * 4] + part[tid * 4 + 1] + part[tid * 4 + 2] + part[tid * 4 + 3];
    __syncthreads();

    if (tid == 0) {
        float sc[E], swb[E];
        for (int i = 0; i < E; i++) {
            float l = logits[i];
            sc[i] = 1.0f / (1.0f + expf(-l));
            swb[i] = sc[i] + ebias[i];
        }
        float gs[8];
        for (int g = 0; g < 8; g++) {
            float m1 = -1e30f, m2 = -1e30f;
            for (int j = 0; j < 8; j++) {
                float v = swb[g * 8 + j];
                if (v > m1) { m2 = m1; m1 = v; }
                else if (v > m2) { m2 = v; }
            }
            gs[g] = m1 + m2;
        }
        bool gsel[8];
        for (int g = 0; g < 8; g++) gsel[g] = false;
        for (int r = 0; r < 4; r++) {
            int best = 0; float bv = -1e30f;
            for (int g = 0; g < 8; g++)
                if (!gsel[g] && gs[g] > bv) { bv = gs[g]; best = g; }
            gsel[best] = true;
        }
        bool picked[E];
        for (int i = 0; i < E; i++) picked[i] = false;
        int idx[TOPK];
        float wsum = 0.0f;
        for (int r = 0; r < TOPK; r++) {
            int best = 0; float bv = -1e30f;
            for (int i = 0; i < E; i++) {
                if (picked[i]) continue;
                float v = gsel[i >> 3] ? swb[i] : 0.0f;
                if (v > bv) { bv = v; best = i; }
            }
            picked[best] = true;
            idx[r] = best;
            wsum += sc[best];
        }
        float inv = 2.5f / (wsum + 1e-20f);
        for (int r = 0; r < TOPK; r++) {
            int ee = idx[r];
            int pos = atomicAdd(&g_cnt[ee], 1);
            g_slot[ee * T + pos] = t * TOPK + r;
            g_tok[ee * T + pos] = t;
            g_wt[ee * T + pos] = sc[ee] * inv;
        }
    }
}

// ================= unified bf16-split MMA GEMM body =================
// C[M=32, N=64] = A[32, KD] * B[N, KD]^T, fp32 in HBM, bf16 hi/lo 3-term MMA.
// 128 threads = 4 warps: warp (wm, wn) handles m16 x n32.
// Double-buffered smem (1 barrier per 32-k chunk), register-staged gmem loads.

__device__ __forceinline__ void ldsm4(unsigned r[4], unsigned addr) {
    asm volatile("ldmatrix.sync.aligned.m8n8.x4.shared.b16 {%0,%1,%2,%3}, [%4];"
        : "=r"(r[0]), "=r"(r[1]), "=r"(r[2]), "=r"(r[3]) : "r"(addr));
}

__device__ __forceinline__ void mma_bf16(float c[4], const unsigned a[4],
                                         unsigned b0, unsigned b1) {
    asm volatile("mma.sync.aligned.m16n8k16.row.col.f32.bf16.bf16.f32 "
        "{%0,%1,%2,%3}, {%4,%5,%6,%7}, {%8,%9}, {%0,%1,%2,%3};"
        : "+f"(c[0]), "+f"(c[1]), "+f"(c[2]), "+f"(c[3])
        : "r"(a[0]), "r"(a[1]), "r"(a[2]), "r"(a[3]), "r"(b0), "r"(b1));
}

__device__ __forceinline__ void cvt_store(float4 v, __nv_bfloat16* hi, __nv_bfloat16* lo) {
    __nv_bfloat162 h01 = __floats2bfloat162_rn(v.x, v.y);
    __nv_bfloat162 h23 = __floats2bfloat162_rn(v.z, v.w);
    float2 f01 = __bfloat1622float2(h01);
    float2 f23 = __bfloat1622float2(h23);
    *(__nv_bfloat162*)hi       = h01;
    *(__nv_bfloat162*)(hi + 2) = h23;
    *(__nv_bfloat162*)lo       = __floats2bfloat162_rn(v.x - f01.x, v.y - f01.y);
    *(__nv_bfloat162*)(lo + 2) = __floats2bfloat162_rn(v.z - f23.x, v.w - f23.y);
}

// smem element layout (bf16 counts):
//   sA: [2 buf][2 plane][32*40]
//   sB: [2 buf][NB][2 plane][64*40]
#define APLANE 1280
#define BPLANE 2560

template<int KD, bool TWOB, int EPI, bool GATHER, bool ATOK, int ASRC, int ODST>
__device__ __forceinline__ void gemm_body(
    int bx, int by, int bz,
    const float* __restrict__ Ain, const float* __restrict__ B1in,
    const float* __restrict__ B2in, float* __restrict__ Oout,
    int ostride, long estrideB, char* dynsmem)
{
    constexpr int NB = TWOB ? 2 : 1;
    constexpr int NCH = KD / 32;

    const float* A = (ASRC == 0) ? Ain : (ASRC == 1) ? (const float*)g_act : (const float*)g_sact;
    float* O = (ODST == 0) ? Oout : (ODST == 1) ? g_act : (ODST == 2) ? g_eo : g_sact;

    int tid = threadIdx.x, lane = tid & 31, wid = tid >> 5;
    int wm = wid & 1, wn = wid >> 1;
    int n0 = bx * 64;

    __nv_bfloat16* sA = (__nv_bfloat16*)dynsmem;
    __nv_bfloat16* sB = sA + 2 * 2 * APLANE;

    __shared__ int s_row[32];
    __shared__ int s_orow[32];
    __shared__ float s_wt[32];

    int mcnt = 32;
    const float* Bp[NB];
    if (GATHER) {
        int e = by;
        int n = g_cnt[e];
        int m0 = bz * 32;
        if (m0 >= n) return;
        mcnt = min(32, n - m0);
        if (tid < 32) {
            bool v = tid < mcnt;
            int idx = e * T + m0 + tid;
            s_row[tid]  = v ? (ATOK ? g_tok[idx] : g_slot[idx]) : -1;
            s_orow[tid] = v ? g_slot[idx] : 0;
            s_wt[tid]   = v ? g_wt[idx] : 0.0f;
        }
        Bp[0] = B1in + (size_t)e * estrideB + (size_t)n0 * KD;
        if (TWOB) Bp[1] = B2in + (size_t)e * estrideB + (size_t)n0 * KD;
    } else {
        int m0 = by * 32;
        if (tid < 32) { s_row[tid] = m0 + tid; s_orow[tid] = m0 + tid; }
        Bp[0] = B1in + (size_t)n0 * KD;
        if (TWOB) Bp[1] = B2in + (size_t)n0 * KD;
    }
    __syncthreads();

    // load-lane mapping
    int ar = tid >> 2, ac = (tid & 3) * 2;   // A: row ar, float4 cols ac, ac+1
    int br = tid >> 1, bc = (tid & 1) * 4;   // B: row br, float4 cols bc..bc+3
    long aoff = (long)s_row[ar];

    float4 pa[2];
    float4 pb[NB][4];

    auto load_chunk = [&](int kt) {
#pragma unroll
        for (int i = 0; i < 2; i++) {
            if (!GATHER || aoff >= 0)
                pa[i] = *(const float4*)&A[(size_t)aoff * KD + kt + (ac + i) * 4];
            else
                pa[i] = make_float4(0.f, 0.f, 0.f, 0.f);
        }
#pragma unroll
        for (int m = 0; m < NB; m++)
#pragma unroll
            for (int i = 0; i < 4; i++)
                pb[m][i] = *(const float4*)&Bp[m][(size_t)br * KD + kt + (bc + i) * 4];
    };

    auto store_chunk = [&](int buf) {
#pragma unroll
        for (int i = 0; i < 2; i++)
            cvt_store(pa[i],
                &sA[(buf * 2 + 0) * APLANE + ar * 40 + (ac + i) * 4],
                &sA[(buf * 2 + 1) * APLANE + ar * 40 + (ac + i) * 4]);
#pragma unroll
        for (int m = 0; m < NB; m++)
#pragma unroll
            for (int i = 0; i < 4; i++)
                cvt_store(pb[m][i],
                    &sB[((buf * NB + m) * 2 + 0) * BPLANE + br * 40 + (bc + i) * 4],
                    &sB[((buf * NB + m) * 2 + 1) * BPLANE + br * 40 + (bc + i) * 4]);
    };

    float acc[NB][4][4];
#pragma unroll
    for (int m = 0; m < NB; m++)
#pragma unroll
        for (int nt = 0; nt < 4; nt++)
#pragma unroll
            for (int j = 0; j < 4; j++) acc[m][nt][j] = 0.0f;

    unsigned aSm = (unsigned)__cvta_generic_to_shared(sA);
    unsigned bSm = (unsigned)__cvta_generic_to_shared(sB);
    int arow_off = ((wm * 16 + (lane & 15)) * 40 + ((lane >> 4) & 1) * 8) * 2;
    int brow_base = wn * 32 + (lane & 7) + ((lane & 16) >> 1);
    int bcol_off = (lane & 8);

    auto compute = [&](int buf) {
        unsigned aHi = aSm + (unsigned)(buf * 2 * APLANE * 2);
        unsigned aLo = aHi + APLANE * 2;
#pragma unroll
        for (int s = 0; s < 2; s++) {
            unsigned ah[4], al[4];
            ldsm4(ah, aHi + arow_off + s * 32);
            ldsm4(al, aLo + arow_off + s * 32);
#pragma unroll
            for (int m = 0; m < NB; m++) {
                unsigned bHi = bSm + (unsigned)(((buf * NB + m) * 2) * BPLANE * 2);
                unsigned bLo = bHi + BPLANE * 2;
                int o0 = (brow_base * 40 + s * 16 + bcol_off) * 2;
                int o1 = ((brow_base + 16) * 40 + s * 16 + bcol_off) * 2;
                unsigned bh[8], bl[8];
                ldsm4(bh, bHi + o0); ldsm4(bh + 4, bHi + o1);
                ldsm4(bl, bLo + o0); ldsm4(bl + 4, bLo + o1);
#pragma unroll
                for (int nt = 0; nt < 4; nt++) {
                    mma_bf16(acc[m][nt], ah, bh[nt * 2], bh[nt * 2 + 1]);
                    mma_bf16(acc[m][nt], ah, bl[nt * 2], bl[nt * 2 + 1]);
                    mma_bf16(acc[m][nt], al, bh[nt * 2], bh[nt * 2 + 1]);
                }
            }
        }
    };

    // double-buffered pipeline: 1 barrier per chunk
    load_chunk(0);
    store_chunk(0);
    __syncthreads();
    for (int ch = 0; ch < NCH; ch++) {
        if (ch + 1 < NCH) load_chunk((ch + 1) * 32);
        compute(ch & 1);
        if (ch + 1 < NCH) {
            store_chunk((ch + 1) & 1);
            __syncthreads();
        }
    }

    // epilogue
    int g = lane >> 2, tq = lane & 3;
#pragma unroll
    for (int half = 0; half < 2; half++) {
        int m = wm * 16 + g + half * 8;
        if (m >= mcnt) continue;
        float w = (EPI == 1) ? s_wt[m] : 0.0f;
        float* op = O + (size_t)s_orow[m] * ostride + n0 + wn * 32 + 2 * tq;
#pragma unroll
        for (int nt = 0; nt < 4; nt++) {
            float v0, v1;
            if (EPI == 0) {
                v0 = silu(acc[0][nt][half * 2])     * acc[1][nt][half * 2];
                v1 = silu(acc[0][nt][half * 2 + 1]) * acc[1][nt][half * 2 + 1];
            } else if (EPI == 1) {
                v0 = acc[0][nt][half * 2] * w;
                v1 = acc[0][nt][half * 2 + 1] * w;
            } else {
                v0 = acc[0][nt][half * 2];
                v1 = acc[0][nt][half * 2 + 1];
            }
            *(float2*)&op[nt * 8] = make_float2(v0, v1);
        }
    }
}

// ---- K1: sharedUp (256 blocks) + routed stageA (4096 blocks) ----
#define K1_SHARED 256
#define K1_TOTAL (K1_SHARED + 8 * 64 * 8)
__global__ __launch_bounds__(128) void k1_kernel(
    const float* __restrict__ x, const float* __restrict__ w1,
    const float* __restrict__ w3, const float* __restrict__ wsg,
    const float* __restrict__ wsu)
{
    extern __shared__ char dyn[];
    int id = blockIdx.x;
    if (id < K1_SHARED) {
        // sact = silu(x @ wsg^T) * (x @ wsu^T)
        gemm_body<1024, true, 0, false, false, 0, 3>(
            id & 31, id >> 5, 0, x, wsg, wsu, nullptr, SI, 0, dyn);
    } else {
        int rid = id - K1_SHARED;
        // act = silu(x_e @ w1^T) * (x_e @ w3^T)  [gather tokens]
        gemm_body<1024, true, 0, true, true, 0, 1>(
            rid & 7, (rid >> 3) & 63, rid >> 9, x, w1, w3, nullptr,
            IDIM, (long)IDIM * H, dyn);
    }
}

// ---- K2: sharedDown (128 blocks) + routed stageB (8192 blocks) ----
#define K2_SHARED 128
#define K2_TOTAL (K2_SHARED + 16 * 64 * 8)
__global__ __launch_bounds__(128) void k2_kernel(
    const float* __restrict__ w2, const float* __restrict__ wsd,
    float* __restrict__ out)
{
    extern __shared__ char dyn[];
    int id = blockIdx.x;
    if (id < K2_SHARED) {
        // out = sact @ wsd^T
        gemm_body<2048, false, 2, false, false, 2, 0>(
            id & 15, id >> 4, 0, nullptr, wsd, wsd, out, H, 0, dyn);
    } else {
        int rid = id - K2_SHARED;
        // eo = (act_e @ w2^T) * cw  [gather slots]
        gemm_body<512, false, 1, true, false, 1, 2>(
            rid & 15, (rid >> 4) & 63, rid >> 10, nullptr, w2, w2, nullptr,
            H, (long)H * IDIM, dyn);
    }
}

// smem: A 2buf*2pl*1280*2B = 10240; B 2buf*NB*2pl*2560*2B
#define K1_SMEM (10240 + 40960)
#define K2_SMEM (10240 + 20480)

// ---- combine: out += sum of the 6 weighted expert outputs per token ----
__global__ void combine_kernel(float* __restrict__ out) {
    int idx = blockIdx.x * 256 + threadIdx.x;
    int t = idx >> 10;
    int h = idx & 1023;
    float s = out[idx];
#pragma unroll
    for (int k = 0; k < TOPK; k++)
        s += g_eo[((size_t)(t * TOPK + k) << 10) + h];
    out[idx] = s;
}

// ---------------- launch ----------------
extern "C" void kernel_launch(void* const* d_in, const int* in_sizes, int n_in,
                              void* d_out, int out_size) {
    const float* x     = (const float*)d_in[0];
    const float* gw    = (const float*)d_in[1];
    const float* ebias = (const float*)d_in[2];
    const float* w1    = (const float*)d_in[3];
    const float* w3    = (const float*)d_in[4];
    const float* w2    = (const float*)d_in[5];
    const float* wsg   = (const float*)d_in[6];
    const float* wsu   = (const float*)d_in[7];
    const float* wsd   = (const float*)d_in[8];
    float* out = (float*)d_out;

    cudaFuncSetAttribute(k1_kernel, cudaFuncAttributeMaxDynamicSharedMemorySize, K1_SMEM);
    cudaFuncSetAttribute(k2_kernel, cudaFuncAttributeMaxDynamicSharedMemorySize, K2_SMEM);

    init_kernel<<<1, 64>>>();
    gate_routing_kernel<<<T, 256>>>(x, gw, ebias);
    k1_kernel<<<K1_TOTAL, 128, K1_SMEM>>>(x, w1, w3, wsg, wsu);
    k2_kernel<<<K2_TOTAL, 128, K2_SMEM>>>(w2, wsd, out);
    combine_kernel<<<(T * H) / 256, 256>>>(out);
}